// round 5
// baseline (speedup 1.0000x reference)
#include <cuda_runtime.h>
#include <mma.h>
#include <cstdint>

using namespace nvcuda;

// ----------------------------------------------------------------------------
// BagModel, warp-autonomous wmma tf32:
//   each warp: 16-row tile. D = X[16,32] @ W1[32,64] (tf32, fp32 acc)
//   epilogue: one bulk acc->SMEM store, per-row s = sum_j relu(D+b1[j])*W2[j]
//   segment mean via atomics; finalize out = sum/cnt + b2.
// ----------------------------------------------------------------------------

#define MAX_BAGS (1 << 18)
__device__ float g_sum[MAX_BAGS];
__device__ float g_cnt[MAX_BAGS];

__global__ void zero_kernel(int nbags) {
    int i = blockIdx.x * blockDim.x + threadIdx.x;
    if (i < nbags) { g_sum[i] = 0.0f; g_cnt[i] = 0.0f; }
}

static constexpr int LDW = 68;   // per-warp buffer row stride (words), mult of 4
static constexpr int LDB = 68;   // B tile row stride
static constexpr int NWARP = 8;  // warps per CTA (256 threads)

__global__ __launch_bounds__(256) void mlp_wmma_kernel(
    const float* __restrict__ x,     // [n, 32]
    const int*   __restrict__ ids,   // [n]
    const float* __restrict__ W1,    // [32, 64]
    const float* __restrict__ b1,    // [64]
    const float* __restrict__ W2,    // [64]
    int n, int nwt)                  // nwt = number of 16-row warp tiles
{
    // per-warp staging/epilogue buffer: 16 rows x 68 words (A tile, then D tile)
    __shared__ __align__(16) float buf[NWARP][16 * LDW];   // 34.8 KB
    __shared__ __align__(16) float sB[32 * LDB];           // 8.7 KB (tf32 W1)
    __shared__ float2 sBW[64];                             // (b1[j], W2[j])

    const int tid  = threadIdx.x;
    const int lane = tid & 31;
    const int warp = tid >> 5;

    for (int idx = tid; idx < 32 * 64; idx += 256) {
        int k = idx >> 6, nn = idx & 63;
        sB[k * LDB + nn] = wmma::__float_to_tf32(W1[k * 64 + nn]);
    }
    if (tid < 64) sBW[tid] = make_float2(b1[tid], W2[tid]);
    __syncthreads();

    float* wbuf = &buf[warp][0];
    const float4* xg = reinterpret_cast<const float4*>(x);
    const int gwarp   = blockIdx.x * NWARP + warp;
    const int gstride = gridDim.x * NWARP;
    const int erow = lane >> 1;          // epilogue: row within tile
    const int ehalf = lane & 1;          // epilogue: column half (0..31 / 32..63)

    for (int wt = gwarp; wt < nwt; wt += gstride) {
        const int row0 = wt * 16;

        // ---- stage A: 16 rows x 32 cols = 128 float4, contiguous in gmem ----
        #pragma unroll
        for (int t = 0; t < 4; t++) {
            int slot = lane + 32 * t;            // 0..127
            int row = slot >> 3, q = slot & 7;
            float4 v = make_float4(0.f, 0.f, 0.f, 0.f);
            if (row0 + row < n) v = xg[(size_t)wt * 128 + slot];
            v.x = wmma::__float_to_tf32(v.x);
            v.y = wmma::__float_to_tf32(v.y);
            v.z = wmma::__float_to_tf32(v.z);
            v.w = wmma::__float_to_tf32(v.w);
            *reinterpret_cast<float4*>(wbuf + row * LDW + q * 4) = v;
        }
        __syncwarp();

        // ---- GEMM: 16x64 = 4 n-tiles, 4 k-steps ----
        wmma::fragment<wmma::accumulator, 16, 16, 8, float> acc[4];
        #pragma unroll
        for (int nt = 0; nt < 4; nt++) wmma::fill_fragment(acc[nt], 0.0f);

        #pragma unroll
        for (int k = 0; k < 4; k++) {
            wmma::fragment<wmma::matrix_a, 16, 16, 8, wmma::precision::tf32,
                           wmma::row_major> af;
            wmma::load_matrix_sync(af, wbuf + k * 8, LDW);
            #pragma unroll
            for (int nt = 0; nt < 4; nt++) {
                wmma::fragment<wmma::matrix_b, 16, 16, 8, wmma::precision::tf32,
                               wmma::row_major> bf;
                wmma::load_matrix_sync(bf, sB + (k * 8) * LDB + nt * 16, LDB);
                wmma::mma_sync(acc[nt], af, bf, acc[nt]);
            }
        }
        __syncwarp();   // all frag loads from wbuf complete before D overwrite

        // ---- bulk store D (16x64) into the same per-warp buffer ----
        #pragma unroll
        for (int nt = 0; nt < 4; nt++)
            wmma::store_matrix_sync(wbuf + nt * 16, acc[nt], LDW,
                                    wmma::mem_row_major);
        __syncwarp();

        // ---- epilogue: lane pair per row; 8 x LDS.128 + relu/W2 reduce ----
        float s = 0.0f;
        const float* rp = wbuf + erow * LDW + ehalf * 32;
        #pragma unroll
        for (int j4 = 0; j4 < 8; j4++) {
            float4 d = *reinterpret_cast<const float4*>(rp + j4 * 4);
            int j = ehalf * 32 + j4 * 4;
            float2 bw;
            bw = sBW[j + 0]; s = fmaf(fmaxf(d.x + bw.x, 0.f), bw.y, s);
            bw = sBW[j + 1]; s = fmaf(fmaxf(d.y + bw.x, 0.f), bw.y, s);
            bw = sBW[j + 2]; s = fmaf(fmaxf(d.z + bw.x, 0.f), bw.y, s);
            bw = sBW[j + 3]; s = fmaf(fmaxf(d.w + bw.x, 0.f), bw.y, s);
        }
        s += __shfl_xor_sync(0xFFFFFFFF, s, 1);   // combine the two halves

        if (ehalf == 0) {
            int r = row0 + erow;
            if (r < n) {
                int bag = ids[r];
                atomicAdd(&g_sum[bag], s);
                atomicAdd(&g_cnt[bag], 1.0f);
            }
        }
        __syncwarp();   // epilogue reads done before next tile's staging
    }
}

__global__ void finalize_kernel(float* __restrict__ out,
                                const float* __restrict__ b2, int nbags)
{
    int b = blockIdx.x * blockDim.x + threadIdx.x;
    if (b < nbags) {
        float c = g_cnt[b];
        c = (c > 0.0f) ? c : 1.0f;
        out[b] = g_sum[b] / c + b2[0];
    }
}

extern "C" void kernel_launch(void* const* d_in, const int* in_sizes, int n_in,
                              void* d_out, int out_size)
{
    const float* x   = (const float*)d_in[0];
    const int*   ids = (const int*)  d_in[1];
    const float* W1  = (const float*)d_in[2];
    const float* b1  = (const float*)d_in[3];
    const float* W2  = (const float*)d_in[4];
    const float* b2  = (const float*)d_in[5];
    float* out = (float*)d_out;

    int n     = in_sizes[1];
    int nbags = out_size;
    int nwt   = (n + 15) / 16;

    zero_kernel<<<(nbags + 255) / 256, 256>>>(nbags);

    int grid = 148 * 4;
    int maxg = (nwt + NWARP - 1) / NWARP;
    if (grid > maxg) grid = maxg;
    mlp_wmma_kernel<<<grid, 32 * NWARP>>>(x, ids, W1, b1, W2, n, nwt);

    finalize_kernel<<<(nbags + 255) / 256, 256>>>(out, b2, nbags);
}

// round 6
// speedup vs baseline: 1.2971x; 1.2971x over previous
#include <cuda_runtime.h>
#include <mma.h>
#include <cstdint>

using namespace nvcuda;

// ----------------------------------------------------------------------------
// BagModel, warp-autonomous wmma tf32, B-in-registers + prefetch:
//   each warp: 16-row tile. D = X[16,32] @ W1[32,64] (tf32, fp32 acc)
//   B fragments live in registers for the whole kernel (W1 is constant).
//   epilogue: one bulk acc->SMEM store, per-row s = sum_j relu(D+b1[j])*W2[j]
//   segment mean via atomics; finalize out = sum/cnt + b2.
// ----------------------------------------------------------------------------

#define MAX_BAGS (1 << 18)
__device__ float g_sum[MAX_BAGS];
__device__ float g_cnt[MAX_BAGS];

__global__ void zero_kernel(int nbags) {
    int i = blockIdx.x * blockDim.x + threadIdx.x;
    if (i < nbags) { g_sum[i] = 0.0f; g_cnt[i] = 0.0f; }
}

static constexpr int LDW = 68;   // per-warp buffer stride; 68 mod 32 == 4 -> A-frag LDS conflict-free
static constexpr int LDB = 68;   // B staging stride
static constexpr int NWARP = 4;  // 128 threads per CTA

__global__ __launch_bounds__(128, 3) void mlp_wmma_kernel(
    const float* __restrict__ x,     // [n, 32]
    const int*   __restrict__ ids,   // [n]
    const float* __restrict__ W1,    // [32, 64]
    const float* __restrict__ b1,    // [64]
    const float* __restrict__ W2,    // [64]
    int n, int nwt)
{
    __shared__ __align__(16) float buf[NWARP][16 * LDW];   // A tile then D tile
    __shared__ __align__(16) float sB[32 * LDB];           // one-time B staging
    __shared__ float2 sBW[64];

    const int tid  = threadIdx.x;
    const int lane = tid & 31;
    const int warp = tid >> 5;

    for (int idx = tid; idx < 32 * 64; idx += 128) {
        int k = idx >> 6, nn = idx & 63;
        sB[k * LDB + nn] = wmma::__float_to_tf32(W1[k * 64 + nn]);
    }
    if (tid < 64) sBW[tid] = make_float2(b1[tid], W2[tid]);
    __syncthreads();

    // ---- B fragments: load ONCE, keep in registers for the whole kernel ----
    wmma::fragment<wmma::matrix_b, 16, 16, 8, wmma::precision::tf32,
                   wmma::row_major> bf[4][4];
    #pragma unroll
    for (int k = 0; k < 4; k++)
        #pragma unroll
        for (int nt = 0; nt < 4; nt++)
            wmma::load_matrix_sync(bf[k][nt], sB + (k * 8) * LDB + nt * 16, LDB);

    float* wbuf = &buf[warp][0];
    const float4* xg = reinterpret_cast<const float4*>(x);
    const int gwarp   = blockIdx.x * NWARP + warp;
    const int gstride = gridDim.x * NWARP;
    const int erow  = lane >> 1;
    const int ehalf = lane & 1;

    // ---- prefetch first tile ----
    float4 pf[4];
    if (gwarp < nwt) {
        #pragma unroll
        for (int t = 0; t < 4; t++) {
            int slot = lane + 32 * t;
            int row = slot >> 3;
            pf[t] = make_float4(0.f, 0.f, 0.f, 0.f);
            if (gwarp * 16 + row < n) pf[t] = xg[(size_t)gwarp * 128 + slot];
        }
    }

    for (int wt = gwarp; wt < nwt; wt += gstride) {
        const int row0 = wt * 16;

        // ---- stage prefetched A (cvt to tf32, STS.128) ----
        #pragma unroll
        for (int t = 0; t < 4; t++) {
            int slot = lane + 32 * t;
            int row = slot >> 3, q = slot & 7;
            float4 v = pf[t];
            v.x = wmma::__float_to_tf32(v.x);
            v.y = wmma::__float_to_tf32(v.y);
            v.z = wmma::__float_to_tf32(v.z);
            v.w = wmma::__float_to_tf32(v.w);
            *reinterpret_cast<float4*>(wbuf + row * LDW + q * 4) = v;
        }

        // ---- prefetch next tile (overlaps MMA + epilogue) ----
        int wtn = wt + gstride;
        if (wtn < nwt) {
            #pragma unroll
            for (int t = 0; t < 4; t++) {
                int slot = lane + 32 * t;
                int row = slot >> 3;
                pf[t] = make_float4(0.f, 0.f, 0.f, 0.f);
                if (wtn * 16 + row < n) pf[t] = xg[(size_t)wtn * 128 + slot];
            }
        }
        __syncwarp();

        // ---- GEMM: 4 k-steps, 4 n-tiles, B from registers ----
        wmma::fragment<wmma::accumulator, 16, 16, 8, float> acc[4];
        #pragma unroll
        for (int nt = 0; nt < 4; nt++) wmma::fill_fragment(acc[nt], 0.0f);

        #pragma unroll
        for (int k = 0; k < 4; k++) {
            wmma::fragment<wmma::matrix_a, 16, 16, 8, wmma::precision::tf32,
                           wmma::row_major> af;
            wmma::load_matrix_sync(af, wbuf + k * 8, LDW);
            #pragma unroll
            for (int nt = 0; nt < 4; nt++)
                wmma::mma_sync(acc[nt], af, bf[k][nt], acc[nt]);
        }
        __syncwarp();

        // ---- bulk store D (16x64) into the same buffer ----
        #pragma unroll
        for (int nt = 0; nt < 4; nt++)
            wmma::store_matrix_sync(wbuf + nt * 16, acc[nt], LDW,
                                    wmma::mem_row_major);
        __syncwarp();

        // ---- epilogue: lane pair per row, 4 independent accumulators ----
        float s0 = 0.f, s1 = 0.f, s2 = 0.f, s3 = 0.f;
        const float* rp = wbuf + erow * LDW + ehalf * 32;
        #pragma unroll
        for (int j4 = 0; j4 < 8; j4++) {
            float4 d = *reinterpret_cast<const float4*>(rp + j4 * 4);
            int j = ehalf * 32 + j4 * 4;
            float2 bw;
            float* sacc = (j4 & 3) == 0 ? &s0 : (j4 & 3) == 1 ? &s1
                        : (j4 & 3) == 2 ? &s2 : &s3;
            bw = sBW[j + 0]; *sacc = fmaf(fmaxf(d.x + bw.x, 0.f), bw.y, *sacc);
            bw = sBW[j + 1]; *sacc = fmaf(fmaxf(d.y + bw.x, 0.f), bw.y, *sacc);
            bw = sBW[j + 2]; *sacc = fmaf(fmaxf(d.z + bw.x, 0.f), bw.y, *sacc);
            bw = sBW[j + 3]; *sacc = fmaf(fmaxf(d.w + bw.x, 0.f), bw.y, *sacc);
        }
        float s = (s0 + s1) + (s2 + s3);
        s += __shfl_xor_sync(0xFFFFFFFF, s, 1);

        if (ehalf == 0) {
            int r = row0 + erow;
            if (r < n) {
                int bag = ids[r];
                atomicAdd(&g_sum[bag], s);
                atomicAdd(&g_cnt[bag], 1.0f);
            }
        }
        __syncwarp();
    }
}

__global__ void finalize_kernel(float* __restrict__ out,
                                const float* __restrict__ b2, int nbags)
{
    int b = blockIdx.x * blockDim.x + threadIdx.x;
    if (b < nbags) {
        float c = g_cnt[b];
        c = (c > 0.0f) ? c : 1.0f;
        out[b] = g_sum[b] / c + b2[0];
    }
}

extern "C" void kernel_launch(void* const* d_in, const int* in_sizes, int n_in,
                              void* d_out, int out_size)
{
    const float* x   = (const float*)d_in[0];
    const int*   ids = (const int*)  d_in[1];
    const float* W1  = (const float*)d_in[2];
    const float* b1  = (const float*)d_in[3];
    const float* W2  = (const float*)d_in[4];
    const float* b2  = (const float*)d_in[5];
    float* out = (float*)d_out;

    int n     = in_sizes[1];
    int nbags = out_size;
    int nwt   = (n + 15) / 16;

    zero_kernel<<<(nbags + 255) / 256, 256>>>(nbags);

    int grid = 148 * 3;
    int maxg = (nwt + NWARP - 1) / NWARP;
    if (grid > maxg) grid = maxg;
    mlp_wmma_kernel<<<grid, 32 * NWARP>>>(x, ids, W1, b1, W2, n, nwt);

    finalize_kernel<<<(nbags + 255) / 256, 256>>>(out, b2, nbags);
}

// round 7
// speedup vs baseline: 1.4245x; 1.0983x over previous
#include <cuda_runtime.h>
#include <mma.h>
#include <cstdint>

using namespace nvcuda;

// ----------------------------------------------------------------------------
// BagModel, warp-autonomous wmma tf32 + cp.async double-buffered staging:
//   each warp: 16-row tile. D = X[16,32] @ W1[32,64] (tf32, fp32 acc)
//   B fragments in registers for the whole kernel.
//   A staged via cp.async (raw fp32), converted to tf32 in-register post-load.
//   epilogue: bulk acc->SMEM store, per-row s = sum_j relu(D+b1[j])*W2[j]
// ----------------------------------------------------------------------------

#define MAX_BAGS (1 << 18)
__device__ float g_sum[MAX_BAGS];
__device__ float g_cnt[MAX_BAGS];

__global__ void zero_kernel(int nbags) {
    int i = blockIdx.x * blockDim.x + threadIdx.x;
    if (i < nbags) { g_sum[i] = 0.0f; g_cnt[i] = 0.0f; }
}

__device__ __forceinline__ uint32_t smem_u32(const void* p) {
    uint32_t a;
    asm("{ .reg .u64 t; cvta.to.shared.u64 t, %1; cvt.u32.u64 %0, t; }"
        : "=r"(a) : "l"(p));
    return a;
}
#define CP_ASYNC16(dst, src) \
    asm volatile("cp.async.ca.shared.global [%0], [%1], 16;" \
                 :: "r"(dst), "l"(src) : "memory")
#define CP_COMMIT() asm volatile("cp.async.commit_group;" ::: "memory")
#define CP_WAIT1()  asm volatile("cp.async.wait_group 1;" ::: "memory")

static constexpr int LDA = 36;   // A stage stride (words); 36 mod 32 = 4 -> conflict-free frags
static constexpr int LDD = 68;   // D scratch stride
static constexpr int LDB = 68;   // B staging stride
static constexpr int NWARP = 4;  // 128 threads

__global__ __launch_bounds__(128, 4) void mlp_wmma_kernel(
    const float* __restrict__ x,     // [n, 32]
    const int*   __restrict__ ids,   // [n]
    const float* __restrict__ W1,    // [32, 64]
    const float* __restrict__ b1,    // [64]
    const float* __restrict__ W2,    // [64]
    int n, int nwt)
{
    __shared__ __align__(16) float sA[NWARP][2][16 * LDA];  // 18.4 KB
    __shared__ __align__(16) float sD[NWARP][16 * LDD];     // 17.4 KB
    __shared__ __align__(16) float sB[32 * LDB];            //  8.7 KB
    __shared__ float2 sBW[64];

    const int tid  = threadIdx.x;
    const int lane = tid & 31;
    const int warp = tid >> 5;

    for (int idx = tid; idx < 32 * 64; idx += 128) {
        int k = idx >> 6, nn = idx & 63;
        sB[k * LDB + nn] = wmma::__float_to_tf32(W1[k * 64 + nn]);
    }
    if (tid < 64) sBW[tid] = make_float2(b1[tid], W2[tid]);
    __syncthreads();

    // B fragments: registers for the whole kernel
    wmma::fragment<wmma::matrix_b, 16, 16, 8, wmma::precision::tf32,
                   wmma::row_major> bf[4][4];
    #pragma unroll
    for (int k = 0; k < 4; k++)
        #pragma unroll
        for (int nt = 0; nt < 4; nt++)
            wmma::load_matrix_sync(bf[k][nt], sB + (k * 8) * LDB + nt * 16, LDB);

    const char* xb = reinterpret_cast<const char*>(x);
    float* dbuf = &sD[warp][0];
    const int gwarp   = blockIdx.x * NWARP + warp;
    const int gstride = gridDim.x * NWARP;
    const int erow  = lane >> 1;
    const int ehalf = lane & 1;

    // per-thread staging slots: 4 x 16B per tile
    const int slot_row[4]   = { (lane) >> 3, (lane + 32) >> 3,
                                (lane + 64) >> 3, (lane + 96) >> 3 };
    const int slot_chunk[4] = { (lane & 7), (lane & 7), (lane & 7), (lane & 7) };

    // prefetch helper (macro-ish lambda)
    auto prefetch = [&](int wt, int pb) {
        if (wt < nwt) {
            const int row0 = wt * 16;
            if (row0 + 16 <= n) {
                #pragma unroll
                for (int t = 0; t < 4; t++) {
                    uint32_t dst = smem_u32(&sA[warp][pb][slot_row[t] * LDA +
                                                          slot_chunk[t] * 4]);
                    const char* src = xb + ((size_t)wt * 2048 +
                                            (size_t)(lane + 32 * t) * 16);
                    CP_ASYNC16(dst, src);
                }
            } else {
                // partial tail tile: synchronous guarded fill
                #pragma unroll
                for (int t = 0; t < 4; t++) {
                    int slot = lane + 32 * t;
                    int row = slot >> 3, q = slot & 7;
                    float4 v = make_float4(0.f, 0.f, 0.f, 0.f);
                    if (row0 + row < n)
                        v = reinterpret_cast<const float4*>(x)[(size_t)wt * 128 + slot];
                    *reinterpret_cast<float4*>(&sA[warp][pb][row * LDA + q * 4]) = v;
                }
            }
        }
        CP_COMMIT();   // always commit (possibly empty) to keep group accounting
    };

    int pb = 0;
    prefetch(gwarp, 0);

    for (int wt = gwarp; wt < nwt; wt += gstride) {
        prefetch(wt + gstride, pb ^ 1);
        CP_WAIT1();
        __syncwarp();

        const float* abuf = &sA[warp][pb][0];

        // GEMM: 4 k-steps, B from registers; A cvt'd to tf32 in-register
        wmma::fragment<wmma::accumulator, 16, 16, 8, float> acc[4];
        #pragma unroll
        for (int nt = 0; nt < 4; nt++) wmma::fill_fragment(acc[nt], 0.0f);

        #pragma unroll
        for (int k = 0; k < 4; k++) {
            wmma::fragment<wmma::matrix_a, 16, 16, 8, wmma::precision::tf32,
                           wmma::row_major> af;
            wmma::load_matrix_sync(af, abuf + k * 8, LDA);
            #pragma unroll
            for (int e = 0; e < af.num_elements; e++)
                af.x[e] = wmma::__float_to_tf32(af.x[e]);
            #pragma unroll
            for (int nt = 0; nt < 4; nt++)
                wmma::mma_sync(acc[nt], af, bf[k][nt], acc[nt]);
        }

        // bulk store D (16x64)
        #pragma unroll
        for (int nt = 0; nt < 4; nt++)
            wmma::store_matrix_sync(dbuf + nt * 16, acc[nt], LDD,
                                    wmma::mem_row_major);
        __syncwarp();

        // epilogue: lane pair per row, 4 independent accumulators
        float s0 = 0.f, s1 = 0.f, s2 = 0.f, s3 = 0.f;
        const float* rp = dbuf + erow * LDD + ehalf * 32;
        #pragma unroll
        for (int j4 = 0; j4 < 8; j4++) {
            float4 d = *reinterpret_cast<const float4*>(rp + j4 * 4);
            int j = ehalf * 32 + j4 * 4;
            float2 bw;
            float* sacc = (j4 & 3) == 0 ? &s0 : (j4 & 3) == 1 ? &s1
                        : (j4 & 3) == 2 ? &s2 : &s3;
            bw = sBW[j + 0]; *sacc = fmaf(fmaxf(d.x + bw.x, 0.f), bw.y, *sacc);
            bw = sBW[j + 1]; *sacc = fmaf(fmaxf(d.y + bw.x, 0.f), bw.y, *sacc);
            bw = sBW[j + 2]; *sacc = fmaf(fmaxf(d.z + bw.x, 0.f), bw.y, *sacc);
            bw = sBW[j + 3]; *sacc = fmaf(fmaxf(d.w + bw.x, 0.f), bw.y, *sacc);
        }
        float s = (s0 + s1) + (s2 + s3);
        s += __shfl_xor_sync(0xFFFFFFFF, s, 1);

        if (ehalf == 0) {
            int r = wt * 16 + erow;
            if (r < n) {
                int bag = ids[r];
                atomicAdd(&g_sum[bag], s);
                atomicAdd(&g_cnt[bag], 1.0f);
            }
        }
        __syncwarp();
        pb ^= 1;
    }
}

__global__ void finalize_kernel(float* __restrict__ out,
                                const float* __restrict__ b2, int nbags)
{
    int b = blockIdx.x * blockDim.x + threadIdx.x;
    if (b < nbags) {
        float c = g_cnt[b];
        c = (c > 0.0f) ? c : 1.0f;
        out[b] = g_sum[b] / c + b2[0];
    }
}

extern "C" void kernel_launch(void* const* d_in, const int* in_sizes, int n_in,
                              void* d_out, int out_size)
{
    const float* x   = (const float*)d_in[0];
    const int*   ids = (const int*)  d_in[1];
    const float* W1  = (const float*)d_in[2];
    const float* b1  = (const float*)d_in[3];
    const float* W2  = (const float*)d_in[4];
    const float* b2  = (const float*)d_in[5];
    float* out = (float*)d_out;

    int n     = in_sizes[1];
    int nbags = out_size;
    int nwt   = (n + 15) / 16;

    zero_kernel<<<(nbags + 255) / 256, 256>>>(nbags);

    int grid = 148 * 4;
    int maxg = (nwt + NWARP - 1) / NWARP;
    if (grid > maxg) grid = maxg;
    mlp_wmma_kernel<<<grid, 32 * NWARP>>>(x, ids, W1, b1, W2, n, nwt);

    finalize_kernel<<<(nbags + 255) / 256, 256>>>(out, b2, nbags);
}